// round 1
// baseline (speedup 1.0000x reference)
#include <cuda_runtime.h>

#define NBIN 512
#define WIN 1022
#define T_IN 127
#define BATCH 64
#define NF (BATCH * T_IN)       // 8128
#define HOP 256
#define T_OUT 62
#define NF3 (BATCH * T_OUT)     // 3968
#define SIG_STRIDE 16672
#define L_OUT 16670
#define J_EVEN 16608

// ---------------- device scratch (no allocations allowed) ----------------
__device__ float  g_frames[NF * 512];        // even-sample frames [f][m], m<511 valid
__device__ float  g_tail[BATCH * 32];        // odd tail samples of frame 126
__device__ float  g_sig[BATCH * SIG_STRIDE]; // decimated signal
__device__ float2 g_W1[512 * 512];           // irfft (even-n) matrix [k][m]
__device__ float2 g_W3[1024 * 512];          // rfft matrix [n][k] = (cos, -sin)
__device__ float  g_synth[WIN];
__device__ float  g_window[1024];            // hann, zero-padded to 1024

// ---------------- setup: hann / synth windows ----------------
__global__ void k_setup() {
    __shared__ float sd[256];
    int tid = threadIdx.x; // 256 threads
    double s = 0.0;
    for (int r = 0; r < 4; r++) {
        int i = r * 256 + tid;
        if (i < WIN) {
            double w = 0.5 - 0.5 * cospi(2.0 * (double)i / 1022.0);
            s += w * w;
        }
    }
    sd[tid] = (float)s;
    __syncthreads();
    for (int n = tid; n < 1024; n += 256) {
        if (n < WIN) {
            double w = 0.5 - 0.5 * cospi(2.0 * (double)n / 1022.0);
            g_window[n] = (float)w;
            g_synth[n]  = (float)(w / (double)sd[n & 255]);
        } else {
            g_window[n] = 0.0f;
        }
    }
}

// ---------------- trig matrix fills ----------------
__global__ void k_fill_w1() {
    int k = blockIdx.x;  // 0..511
    const double invN = 1.0 / 1022.0;
    for (int m = threadIdx.x; m < 512; m += blockDim.x) {
        float2 v = make_float2(0.0f, 0.0f);
        if (m < 511) {
            if (k == 0 || k == 511) {
                v = make_float2((float)invN, 0.0f);   // DC / Nyquist (even n -> cos=+1), imag ignored
            } else {
                int r = (k * m) % 511;
                double sn, cs;
                sincospi(2.0 * (double)r / 511.0, &sn, &cs);
                v = make_float2((float)(2.0 * invN * cs), (float)(-2.0 * invN * sn));
            }
        }
        g_W1[k * 512 + m] = v;
    }
}

__global__ void k_fill_w3() {
    int n = blockIdx.x;  // 0..1023
    for (int k = threadIdx.x; k < 512; k += blockDim.x) {
        float2 v = make_float2(0.0f, 0.0f);
        if (n < WIN) {
            int r = (n * k) % WIN;          // angle = 2*pi*r/1022 = pi * (r/511)
            double sn, cs;
            sincospi((double)r / 511.0, &sn, &cs);
            v = make_float2((float)cs, (float)(-sn));
        }
        g_W3[n * 512 + k] = v;
    }
}

// ---------------- pass 1: irfft at even samples (GEMM) ----------------
// C[f][m] = sum_k re[f][k]*W1c[k][m] + im[f][k]*W1s[k][m], then * SYNTH[2m]
__global__ __launch_bounds__(256) void k_pass1(const float2* __restrict__ inF2) {
    __shared__ float2 Asm[32][64];   // [k_local][f_local]
    __shared__ float2 Bsm[32][64];   // [k_local][m_local]
    int tid = threadIdx.x;
    int m0 = blockIdx.x * 64;
    int f0 = blockIdx.y * 64;
    int tx = tid & 15, ty = tid >> 4;

    float acc[4][4];
#pragma unroll
    for (int i = 0; i < 4; i++)
#pragma unroll
        for (int j = 0; j < 4; j++) acc[i][j] = 0.0f;

    for (int kc = 0; kc < 512; kc += 32) {
#pragma unroll
        for (int r = 0; r < 8; r++) {
            int e = r * 256 + tid;
            int fl = e & 63, kl = e >> 6;
            int f = f0 + fl;
            int b = f / 127, t = f - b * 127;
            Asm[kl][fl] = inF2[(b * 512 + (kc + kl)) * 127 + t];
        }
#pragma unroll
        for (int r = 0; r < 8; r++) {
            int e = r * 256 + tid;
            int ml = e & 63, kl = e >> 6;
            Bsm[kl][ml] = g_W1[(kc + kl) * 512 + (m0 + ml)];
        }
        __syncthreads();
#pragma unroll
        for (int kk = 0; kk < 32; kk++) {
            float4 a0 = ((const float4*)Asm[kk])[ty * 2];
            float4 a1 = ((const float4*)Asm[kk])[ty * 2 + 1];
            float4 b0 = ((const float4*)Bsm[kk])[tx * 2];
            float4 b1 = ((const float4*)Bsm[kk])[tx * 2 + 1];
            float ar[4] = {a0.x, a0.z, a1.x, a1.z};
            float ai[4] = {a0.y, a0.w, a1.y, a1.w};
            float bc[4] = {b0.x, b0.z, b1.x, b1.z};
            float bs[4] = {b0.y, b0.w, b1.y, b1.w};
#pragma unroll
            for (int i = 0; i < 4; i++)
#pragma unroll
                for (int j = 0; j < 4; j++) {
                    acc[i][j] = fmaf(ar[i], bc[j], acc[i][j]);
                    acc[i][j] = fmaf(ai[i], bs[j], acc[i][j]);
                }
        }
        __syncthreads();
    }

#pragma unroll
    for (int i = 0; i < 4; i++) {
        int f = f0 + ty * 4 + i;
#pragma unroll
        for (int j = 0; j < 4; j++) {
            int m = m0 + tx * 4 + j;
            if (m < 511) g_frames[f * 512 + m] = acc[i][j] * g_synth[2 * m];
        }
    }
}

// ---------------- pass 1b: odd tail samples of frame 126 ----------------
__global__ void k_pass1b(const float2* __restrict__ inF2) {
    __shared__ float2 sb[512];
    __shared__ float part[31][8];
    int b = blockIdx.x;
    int tid = threadIdx.x;   // 256
    for (int k = tid; k < 512; k += 256)
        sb[k] = inF2[(b * 512 + k) * 127 + 126];
    __syncthreads();
    int ni = tid >> 3, kp = tid & 7;
    if (ni < 31) {
        int n = 961 + 2 * ni;
        float acc = 0.0f;
        for (int k = kp; k < 512; k += 8) {
            float2 x = sb[k];
            float2 w = g_W3[n * 512 + k];       // (cos, -sin); sin cols are 0 at k=0,511
            float coef = (k == 0 || k == 511) ? 1.0f : 2.0f;
            acc += coef * (x.x * w.x + x.y * w.y);
        }
        part[ni][kp] = acc;
    }
    __syncthreads();
    if (tid < 31) {
        float s = 0.0f;
#pragma unroll
        for (int q = 0; q < 8; q++) s += part[tid][q];
        g_tail[b * 32 + tid] = s * (1.0f / 1022.0f) * g_synth[961 + 2 * tid];
    }
}

// ---------------- pass 2: overlap-add at kept positions ----------------
__global__ void k_pass2() {
    int idx = blockIdx.x * blockDim.x + threadIdx.x;
    if (idx >= BATCH * L_OUT) return;
    int b = idx / L_OUT, j = idx - b * L_OUT;
    float v;
    if (j < J_EVEN) {
        int p = 2 * j;
        int t_hi = min(126, p >> 8);
        int t_lo = max(0, p - 766) >> 8;   // ceil((p-1021)/256) clamped at 0
        float acc = 0.0f;
        for (int t = t_lo; t <= t_hi; t++) {
            int m = j - (t << 7);          // (p - 256t)/2
            acc += g_frames[(b * 127 + t) * 512 + m];
        }
        v = acc;
    } else {
        int n = j - 15648;                 // 960..1021, frame 126 only
        if (n & 1) v = g_tail[b * 32 + ((n - 961) >> 1)];
        else       v = g_frames[(b * 127 + 126) * 512 + (n >> 1)];
    }
    g_sig[b * SIG_STRIDE + j] = v;
}

// ---------------- pass 3: window + rfft (GEMM, complex out) ----------------
__global__ __launch_bounds__(256) void k_pass3(float2* __restrict__ outF2) {
    __shared__ float  Asm[32][65];   // [n_local][f_local], padded
    __shared__ float2 Bsm[32][64];   // [n_local][k_local]
    int tid = threadIdx.x;
    int k0 = blockIdx.x * 64;
    int f0 = blockIdx.y * 64;
    int tx = tid & 15, ty = tid >> 4;

    float2 acc[4][4];
#pragma unroll
    for (int i = 0; i < 4; i++)
#pragma unroll
        for (int j = 0; j < 4; j++) acc[i][j] = make_float2(0.0f, 0.0f);

    for (int nc = 0; nc < 1024; nc += 32) {
#pragma unroll
        for (int r = 0; r < 8; r++) {
            int e = r * 256 + tid;
            int nl = e & 31, fl = e >> 5;
            int f = f0 + fl;
            int b = f / 62, t = f - b * 62;
            Asm[nl][fl] = g_sig[b * SIG_STRIDE + t * 256 + nc + nl] * g_window[nc + nl];
        }
#pragma unroll
        for (int r = 0; r < 8; r++) {
            int e = r * 256 + tid;
            int kl = e & 63, nl = e >> 6;
            Bsm[nl][kl] = g_W3[(nc + nl) * 512 + (k0 + kl)];
        }
        __syncthreads();
#pragma unroll
        for (int kk = 0; kk < 32; kk++) {
            float a[4];
#pragma unroll
            for (int i = 0; i < 4; i++) a[i] = Asm[kk][ty * 4 + i];
            float4 b0 = ((const float4*)Bsm[kk])[tx * 2];
            float4 b1 = ((const float4*)Bsm[kk])[tx * 2 + 1];
            float bc[4] = {b0.x, b0.z, b1.x, b1.z};
            float bs[4] = {b0.y, b0.w, b1.y, b1.w};
#pragma unroll
            for (int i = 0; i < 4; i++)
#pragma unroll
                for (int j = 0; j < 4; j++) {
                    acc[i][j].x = fmaf(a[i], bc[j], acc[i][j].x);
                    acc[i][j].y = fmaf(a[i], bs[j], acc[i][j].y);
                }
        }
        __syncthreads();
    }

#pragma unroll
    for (int i = 0; i < 4; i++) {
        int f = f0 + ty * 4 + i;
        int b = f / 62, t = f - b * 62;
#pragma unroll
        for (int j = 0; j < 4; j++) {
            int k = k0 + tx * 4 + j;
            outF2[(b * 512 + k) * 62 + t] = acc[i][j];
        }
    }
}

// ---------------- launch ----------------
extern "C" void kernel_launch(void* const* d_in, const int* in_sizes, int n_in,
                              void* d_out, int out_size) {
    (void)in_sizes; (void)n_in; (void)out_size;
    const float2* inF2 = (const float2*)d_in[0];
    float2* outF2 = (float2*)d_out;

    k_setup<<<1, 256>>>();
    k_fill_w1<<<512, 256>>>();
    k_fill_w3<<<1024, 256>>>();
    k_pass1<<<dim3(8, 127), 256>>>(inF2);
    k_pass1b<<<64, 256>>>(inF2);
    k_pass2<<<(BATCH * L_OUT + 255) / 256, 256>>>();
    k_pass3<<<dim3(8, 62), 256>>>(outF2);
}

// round 2
// speedup vs baseline: 1.4152x; 1.4152x over previous
#include <cuda_runtime.h>

#define NBIN 512
#define WIN 1022
#define T_IN 127
#define BATCH 64
#define NF (BATCH * T_IN)       // 8128
#define HOP 256
#define T_OUT 62
#define SIG_STRIDE 16672
#define L_OUT 16670
#define J_EVEN 16608

// ---------------- device scratch ----------------
__device__ float g_frames[NF * 512];
__device__ float g_tail[BATCH * 32];
__device__ float g_sig[BATCH * SIG_STRIDE];
__device__ float g_W1c[512 * 512];           // irfft even-n: 2/N cos (1/N at k=0,511)
__device__ float g_W1s[512 * 512];           // irfft even-n: -2/N sin (0 at k=0,511)
__device__ float g_W3c[1024 * 512];          // rfft: cos
__device__ float g_W3s[1024 * 512];          // rfft: -sin
__device__ float g_synth[WIN];
__device__ float g_synth2[512];              // synth[2m]
__device__ float g_window[1024];

// ---------------- packed f32x2 helpers ----------------
__device__ __forceinline__ unsigned long long pk2(float lo, float hi) {
    unsigned long long r;
    asm("mov.b64 %0, {%1, %2};" : "=l"(r) : "f"(lo), "f"(hi));
    return r;
}
__device__ __forceinline__ void fma2(unsigned long long& d, unsigned long long a, unsigned long long b) {
    asm("fma.rn.f32x2 %0, %1, %2, %0;" : "+l"(d) : "l"(a), "l"(b));
}
__device__ __forceinline__ float2 upk(unsigned long long v) {
    float2 f;
    asm("mov.b64 {%0, %1}, %2;" : "=f"(f.x), "=f"(f.y) : "l"(v));
    return f;
}

// ---------------- setup ----------------
__global__ void k_setup() {
    __shared__ float sd[256];
    int tid = threadIdx.x;
    double s = 0.0;
    for (int r = 0; r < 4; r++) {
        int i = r * 256 + tid;
        if (i < WIN) {
            double w = 0.5 - 0.5 * cospi(2.0 * (double)i / 1022.0);
            s += w * w;
        }
    }
    sd[tid] = (float)s;
    __syncthreads();
    for (int n = tid; n < 1024; n += 256) {
        if (n < WIN) {
            double w = 0.5 - 0.5 * cospi(2.0 * (double)n / 1022.0);
            float sv = (float)(w / (double)sd[n & 255]);
            g_window[n] = (float)w;
            g_synth[n] = sv;
            if ((n & 1) == 0) g_synth2[n >> 1] = sv;
        } else {
            g_window[n] = 0.0f;
        }
    }
}

__global__ void k_fill_w1() {
    int k = blockIdx.x;
    const float invN = 1.0f / 1022.0f;
    for (int m = threadIdx.x; m < 512; m += blockDim.x) {
        float vc = 0.0f, vs = 0.0f;
        if (m < 511) {
            if (k == 0 || k == 511) {
                vc = invN;
            } else {
                int r = (k * m) % 511;
                float sn, cs;
                sincospif(2.0f * (float)r / 511.0f, &sn, &cs);
                vc = 2.0f * invN * cs;
                vs = -2.0f * invN * sn;
            }
        }
        g_W1c[k * 512 + m] = vc;
        g_W1s[k * 512 + m] = vs;
    }
}

__global__ void k_fill_w3() {
    int n = blockIdx.x;
    for (int k = threadIdx.x; k < 512; k += blockDim.x) {
        float vc = 0.0f, vs = 0.0f;
        if (n < WIN) {
            int r = (n * k) % WIN;
            float sn, cs;
            sincospif((float)r / 511.0f, &sn, &cs);
            vc = cs; vs = -sn;
        }
        g_W3c[n * 512 + k] = vc;
        g_W3s[n * 512 + k] = vs;
    }
}

// ---------------- pass 1: irfft at even samples, 128x128 tile, 8x8/thread ----------------
#define BK1 16
__global__ __launch_bounds__(256, 2) void k_pass1(const float2* __restrict__ inF2) {
    __shared__ float Ar[BK1][128], Ai[BK1][128], Bc[BK1][128], Bs[BK1][128];
    int tid = threadIdx.x;
    int m0 = blockIdx.x * 128;
    int f0 = blockIdx.y * 128;
    int tx = tid & 15, ty = tid >> 4;

    unsigned long long acc[8][4];
#pragma unroll
    for (int i = 0; i < 8; i++)
#pragma unroll
        for (int j = 0; j < 4; j++) acc[i][j] = 0ULL;

    for (int kc = 0; kc < 512; kc += BK1) {
#pragma unroll
        for (int r = 0; r < 8; r++) {
            int e = r * 256 + tid;
            int fl = e & 127, kl = e >> 7;
            int f = min(f0 + fl, NF - 1);
            int b = f / 127, t = f - b * 127;
            float2 v = inF2[(b * 512 + kc + kl) * 127 + t];
            Ar[kl][fl] = v.x;
            Ai[kl][fl] = v.y;
        }
#pragma unroll
        for (int r = 0; r < 2; r++) {
            int e = r * 256 + tid;
            int q = e & 31, kl = e >> 5;
            ((float4*)&Bc[kl][0])[q] = ((const float4*)(g_W1c + (kc + kl) * 512 + m0))[q];
            ((float4*)&Bs[kl][0])[q] = ((const float4*)(g_W1s + (kc + kl) * 512 + m0))[q];
        }
        __syncthreads();
#pragma unroll 8
        for (int kk = 0; kk < BK1; kk++) {
            float4 arL = ((const float4*)Ar[kk])[ty];
            float4 arH = ((const float4*)Ar[kk])[16 + ty];
            float4 aiL = ((const float4*)Ai[kk])[ty];
            float4 aiH = ((const float4*)Ai[kk])[16 + ty];
            float4 bcL = ((const float4*)Bc[kk])[tx];
            float4 bcH = ((const float4*)Bc[kk])[16 + tx];
            float4 bsL = ((const float4*)Bs[kk])[tx];
            float4 bsH = ((const float4*)Bs[kk])[16 + tx];
            unsigned long long bc0 = pk2(bcL.x, bcL.y), bc1 = pk2(bcL.z, bcL.w);
            unsigned long long bc2 = pk2(bcH.x, bcH.y), bc3 = pk2(bcH.z, bcH.w);
            unsigned long long bs0 = pk2(bsL.x, bsL.y), bs1 = pk2(bsL.z, bsL.w);
            unsigned long long bs2 = pk2(bsH.x, bsH.y), bs3 = pk2(bsH.z, bsH.w);
            float arv[8] = {arL.x, arL.y, arL.z, arL.w, arH.x, arH.y, arH.z, arH.w};
            float aiv[8] = {aiL.x, aiL.y, aiL.z, aiL.w, aiH.x, aiH.y, aiH.z, aiH.w};
#pragma unroll
            for (int i = 0; i < 8; i++) {
                unsigned long long ar2 = pk2(arv[i], arv[i]);
                unsigned long long ai2 = pk2(aiv[i], aiv[i]);
                fma2(acc[i][0], ar2, bc0); fma2(acc[i][0], ai2, bs0);
                fma2(acc[i][1], ar2, bc1); fma2(acc[i][1], ai2, bs1);
                fma2(acc[i][2], ar2, bc2); fma2(acc[i][2], ai2, bs2);
                fma2(acc[i][3], ar2, bc3); fma2(acc[i][3], ai2, bs3);
            }
        }
        __syncthreads();
    }

#pragma unroll
    for (int i = 0; i < 8; i++) {
        int f = f0 + (i < 4 ? ty * 4 + i : 64 + ty * 4 + i - 4);
        if (f < NF) {
#pragma unroll
            for (int jj = 0; jj < 4; jj++) {
                int m = (jj < 2) ? (m0 + tx * 4 + 2 * jj) : (m0 + 64 + tx * 4 + 2 * (jj - 2));
                float2 v = upk(acc[i][jj]);
                g_frames[f * 512 + m] = v.x * g_synth2[m];
                if (m + 1 < 511) g_frames[f * 512 + m + 1] = v.y * g_synth2[m + 1];
            }
        }
    }
}

// ---------------- pass 1b: odd tail of frame 126 ----------------
__global__ void k_pass1b(const float2* __restrict__ inF2) {
    __shared__ float2 sb[512];
    __shared__ float part[31][8];
    int b = blockIdx.x;
    int tid = threadIdx.x;
    for (int k = tid; k < 512; k += 256)
        sb[k] = inF2[(b * 512 + k) * 127 + 126];
    __syncthreads();
    int ni = tid >> 3, kp = tid & 7;
    if (ni < 31) {
        int n = 961 + 2 * ni;
        float acc = 0.0f;
        for (int k = kp; k < 512; k += 8) {
            float2 x = sb[k];
            float coef = (k == 0 || k == 511) ? 1.0f : 2.0f;
            acc += coef * (x.x * g_W3c[n * 512 + k] + x.y * g_W3s[n * 512 + k]);
        }
        part[ni][kp] = acc;
    }
    __syncthreads();
    if (tid < 31) {
        float s = 0.0f;
#pragma unroll
        for (int q = 0; q < 8; q++) s += part[tid][q];
        g_tail[b * 32 + tid] = s * (1.0f / 1022.0f) * g_synth[961 + 2 * tid];
    }
}

// ---------------- pass 2: overlap-add ----------------
__global__ void k_pass2() {
    int idx = blockIdx.x * blockDim.x + threadIdx.x;
    if (idx >= BATCH * L_OUT) return;
    int b = idx / L_OUT, j = idx - b * L_OUT;
    float v;
    if (j < J_EVEN) {
        int p = 2 * j;
        int t_hi = min(126, p >> 8);
        int t_lo = max(0, p - 766) >> 8;
        float acc = 0.0f;
        for (int t = t_lo; t <= t_hi; t++) {
            int m = j - (t << 7);
            acc += g_frames[(b * 127 + t) * 512 + m];
        }
        v = acc;
    } else {
        int n = j - 15648;
        if (n & 1) v = g_tail[b * 32 + ((n - 961) >> 1)];
        else       v = g_frames[(b * 127 + 126) * 512 + (n >> 1)];
    }
    g_sig[b * SIG_STRIDE + j] = v;
}

// ---------------- pass 3: window + rfft, 128f x 64k tile, 8x4(complex)/thread ----------------
#define BK3 32
__global__ __launch_bounds__(256, 2) void k_pass3(float2* __restrict__ outF2) {
    __shared__ float Aw[BK3][128], Bc[BK3][64], Bs[BK3][64];
    int tid = threadIdx.x;
    int k0 = blockIdx.x * 64;
    int f0 = blockIdx.y * 128;
    int tx = tid & 15, ty = tid >> 4;

    unsigned long long acc[8][4];
#pragma unroll
    for (int i = 0; i < 8; i++)
#pragma unroll
        for (int j = 0; j < 4; j++) acc[i][j] = 0ULL;

    for (int nc = 0; nc < 1024; nc += BK3) {
#pragma unroll
        for (int r = 0; r < 16; r++) {
            int e = r * 256 + tid;
            int fl = e & 127, nl = e >> 7;
            int f = f0 + fl;
            int b = f / 62, t = f - b * 62;
            Aw[nl][fl] = g_sig[b * SIG_STRIDE + t * 256 + nc + nl] * g_window[nc + nl];
        }
#pragma unroll
        for (int r = 0; r < 2; r++) {
            int e = r * 256 + tid;
            int q = e & 15, nl = e >> 4;
            ((float4*)&Bc[nl][0])[q] = ((const float4*)(g_W3c + (nc + nl) * 512 + k0))[q];
            ((float4*)&Bs[nl][0])[q] = ((const float4*)(g_W3s + (nc + nl) * 512 + k0))[q];
        }
        __syncthreads();
#pragma unroll 8
        for (int kk = 0; kk < BK3; kk++) {
            float4 aL = ((const float4*)Aw[kk])[ty];
            float4 aH = ((const float4*)Aw[kk])[16 + ty];
            float4 bc4 = ((const float4*)Bc[kk])[tx];
            float4 bs4 = ((const float4*)Bs[kk])[tx];
            unsigned long long b0 = pk2(bc4.x, bs4.x), b1 = pk2(bc4.y, bs4.y);
            unsigned long long b2 = pk2(bc4.z, bs4.z), b3 = pk2(bc4.w, bs4.w);
            float av[8] = {aL.x, aL.y, aL.z, aL.w, aH.x, aH.y, aH.z, aH.w};
#pragma unroll
            for (int i = 0; i < 8; i++) {
                unsigned long long a2 = pk2(av[i], av[i]);
                fma2(acc[i][0], a2, b0);
                fma2(acc[i][1], a2, b1);
                fma2(acc[i][2], a2, b2);
                fma2(acc[i][3], a2, b3);
            }
        }
        __syncthreads();
    }

#pragma unroll
    for (int i = 0; i < 8; i++) {
        int f = f0 + (i < 4 ? ty * 4 + i : 64 + ty * 4 + i - 4);
        int b = f / 62, t = f - b * 62;
#pragma unroll
        for (int j = 0; j < 4; j++) {
            int k = k0 + tx * 4 + j;
            float2 v = upk(acc[i][j]);
            outF2[(b * 512 + k) * 62 + t] = v;
        }
    }
}

// ---------------- launch ----------------
extern "C" void kernel_launch(void* const* d_in, const int* in_sizes, int n_in,
                              void* d_out, int out_size) {
    (void)in_sizes; (void)n_in; (void)out_size;
    const float2* inF2 = (const float2*)d_in[0];
    float2* outF2 = (float2*)d_out;

    k_setup<<<1, 256>>>();
    k_fill_w1<<<512, 256>>>();
    k_fill_w3<<<1024, 256>>>();
    k_pass1<<<dim3(4, 64), 256>>>(inF2);
    k_pass1b<<<64, 256>>>(inF2);
    k_pass2<<<(BATCH * L_OUT + 255) / 256, 256>>>();
    k_pass3<<<dim3(8, 31), 256>>>(outF2);
}